// round 7
// baseline (speedup 1.0000x reference)
#include <cuda_runtime.h>

#define TSEQ 4096
#define HID  1024
#define NH   16
#define HD   64
#define STR  68

// Scratch for Q, K, V in [head][token][dh] layout (16 MB each).
__device__ float g_q[NH * TSEQ * HD];
__device__ float g_k[NH * TSEQ * HD];
__device__ float g_v[NH * TSEQ * HD];

// ---------------------------------------------------------------------------
// Packed fp32x2 helpers (sm_10x).
// ---------------------------------------------------------------------------
__device__ __forceinline__ unsigned long long dup2(float x) {
    unsigned long long r;
    unsigned u = __float_as_uint(x);
    asm("mov.b64 %0, {%1, %1};" : "=l"(r) : "r"(u));
    return r;
}
__device__ __forceinline__ void fma2(unsigned long long& d,
                                     unsigned long long a, unsigned long long b) {
    asm("fma.rn.f32x2 %0, %1, %2, %0;" : "+l"(d) : "l"(a), "l"(b));
}
__device__ __forceinline__ unsigned long long mul2(unsigned long long a,
                                                   unsigned long long b) {
    unsigned long long r;
    asm("mul.rn.f32x2 %0, %1, %2;" : "=l"(r) : "l"(a), "l"(b));
    return r;
}
__device__ __forceinline__ float2 unpk(unsigned long long v) {
    unsigned lo, hi;
    asm("mov.b64 {%0, %1}, %2;" : "=r"(lo), "=r"(hi) : "l"(v));
    return make_float2(__uint_as_float(lo), __uint_as_float(hi));
}

// ---------------------------------------------------------------------------
// Kernel 1: QKV GEMM. 128x128 tile, BK=16, 256 threads, 8x8 frag, f32x2,
// B pairs via ulonglong2 shared loads, 2 CTAs/SM.
// ---------------------------------------------------------------------------
#define GSTR 132

__global__ __launch_bounds__(256, 2) void qkv_gemm_kernel(const float* __restrict__ x,
                                                          const float* __restrict__ W) {
    __shared__ float As[16][GSTR];   // As[k][m]
    __shared__ float Bs[16][GSTR];   // Bs[k][n]

    const int tid = threadIdx.x;
    const int tx = tid & 15, ty = tid >> 4;
    const int n0 = blockIdx.x * 128;
    const int m0 = blockIdx.y * 128;

    const int arow = tid >> 1;            // 0..127
    const int acol = (tid & 1) << 3;      // 0 or 8
    const int brow = tid >> 4;            // 0..15
    const int bcol = (tid & 15) << 3;     // 0..120

    float4 a0 = *(const float4*)&x[(m0 + arow) * HID + acol];
    float4 a1 = *(const float4*)&x[(m0 + arow) * HID + acol + 4];
    float4 b0 = *(const float4*)&W[brow * (3 * HID) + n0 + bcol];
    float4 b1 = *(const float4*)&W[brow * (3 * HID) + n0 + bcol + 4];

    unsigned long long acc[8][4] = {};

    for (int k0 = 0; k0 < HID; k0 += 16) {
        As[acol + 0][arow] = a0.x; As[acol + 1][arow] = a0.y;
        As[acol + 2][arow] = a0.z; As[acol + 3][arow] = a0.w;
        As[acol + 4][arow] = a1.x; As[acol + 5][arow] = a1.y;
        As[acol + 6][arow] = a1.z; As[acol + 7][arow] = a1.w;
        *(float4*)&Bs[brow][bcol] = b0;
        *(float4*)&Bs[brow][bcol + 4] = b1;
        __syncthreads();

        if (k0 + 16 < HID) {
            a0 = *(const float4*)&x[(m0 + arow) * HID + k0 + 16 + acol];
            a1 = *(const float4*)&x[(m0 + arow) * HID + k0 + 16 + acol + 4];
            b0 = *(const float4*)&W[(k0 + 16 + brow) * (3 * HID) + n0 + bcol];
            b1 = *(const float4*)&W[(k0 + 16 + brow) * (3 * HID) + n0 + bcol + 4];
        }

#pragma unroll
        for (int kk = 0; kk < 16; kk++) {
            float4 aA = *(float4*)&As[kk][ty << 3];
            float4 aB = *(float4*)&As[kk][(ty << 3) + 4];
            ulonglong2 bA = *(ulonglong2*)&Bs[kk][tx << 3];
            ulonglong2 bB = *(ulonglong2*)&Bs[kk][(tx << 3) + 4];
            unsigned long long bp[4] = {bA.x, bA.y, bB.x, bB.y};
            float av[8] = {aA.x, aA.y, aA.z, aA.w, aB.x, aB.y, aB.z, aB.w};
#pragma unroll
            for (int i = 0; i < 8; i++) {
                unsigned long long ad = dup2(av[i]);
#pragma unroll
                for (int jp = 0; jp < 4; jp++) fma2(acc[i][jp], ad, bp[jp]);
            }
        }
        __syncthreads();
    }

    const int s = n0 / HID;
    float* dst = (s == 0) ? g_q : (s == 1) ? g_k : g_v;
    const int col = (n0 % HID) + (tx << 3);
    const int hh = col / HD;
    const int dd = col % HD;

#pragma unroll
    for (int i = 0; i < 8; i++) {
        const int t = m0 + (ty << 3) + i;
        float2 e0 = unpk(acc[i][0]), e1 = unpk(acc[i][1]);
        float2 e2 = unpk(acc[i][2]), e3 = unpk(acc[i][3]);
        float* p = &dst[(hh * TSEQ + t) * HD + dd];
        *(float4*)p       = make_float4(e0.x, e0.y, e1.x, e1.y);
        *(float4*)(p + 4) = make_float4(e2.x, e2.y, e3.x, e3.y);
    }
}

// ---------------------------------------------------------------------------
// Kernel 2: flash attention, 64q x 64k tile, 256 threads, 3 CTAs/SM.
// Register softmax; P^T overwrites the K buffer (dead after QK).
// Thread grid 16(tx: cols/dims) x 16(ty: row groups), 4x4 fragments,
// accumulator pairs along tx via f32x2.
// ---------------------------------------------------------------------------
#define ATTN_SMEM_FLOATS (3 * 64 * STR + 128)
#define ATTN_SMEM_BYTES  (ATTN_SMEM_FLOATS * 4)

__global__ __launch_bounds__(256, 3) void flash_attn_kernel(float* __restrict__ out) {
    extern __shared__ float smf[];
    float* Qs   = smf;                 // [d][r]  64 x STR (Q^T, pre-scaled)
    float* KPs  = Qs + 64 * STR;       // [d][c] K^T, then [c][r] P^T
    float* Vs   = KPs + 64 * STR;      // [k][d]
    float* mrow = Vs + 64 * STR;       // [64]
    float* lrow = mrow + 64;           // [64]

    const int tid = threadIdx.x;
    const int tx = tid & 15, ty = tid >> 4;
    const int h  = blockIdx.y;
    const int q0 = blockIdx.x * 64;

    const float* Qg = g_q + h * TSEQ * HD;
    const float* Kg = g_k + h * TSEQ * HD;
    const float* Vg = g_v + h * TSEQ * HD;

    const int lr = tid >> 2;           // 0..63 load row
    const int ds = (tid & 3) << 4;     // 0,16,32,48

    // Q^T, scaled by 1/sqrt(64)
#pragma unroll
    for (int c = 0; c < 4; c++) {
        const int d = ds + c * 4;
        float4 v = *(const float4*)&Qg[(q0 + lr) * HD + d];
        Qs[(d + 0) * STR + lr] = v.x * 0.125f;
        Qs[(d + 1) * STR + lr] = v.y * 0.125f;
        Qs[(d + 2) * STR + lr] = v.z * 0.125f;
        Qs[(d + 3) * STR + lr] = v.w * 0.125f;
    }
    if (tid < 64) { mrow[tid] = -1e30f; lrow[tid] = 0.f; }

    unsigned long long op[4][2] = {};   // O: rows ty*4+i, dim pairs tx*4+2jp

    for (int kb = 0; kb < TSEQ / 64; kb++) {
        const int c0 = kb * 64;
        __syncthreads();   // prev PV done reading KPs/Vs (and Q/stats on iter 0)

        // Stage K^T into KPs, V into Vs
#pragma unroll
        for (int c = 0; c < 4; c++) {
            const int d = ds + c * 4;
            float4 kv = *(const float4*)&Kg[(c0 + lr) * HD + d];
            KPs[(d + 0) * STR + lr] = kv.x;
            KPs[(d + 1) * STR + lr] = kv.y;
            KPs[(d + 2) * STR + lr] = kv.z;
            KPs[(d + 3) * STR + lr] = kv.w;
            *(float4*)&Vs[lr * STR + d] = *(const float4*)&Vg[(c0 + lr) * HD + d];
        }
        __syncthreads();

        // S = Q @ K^T : acc[i][jp] = S[ty*4+i][tx*4+2jp .. +1]
        unsigned long long acc[4][2] = {};
#pragma unroll 8
        for (int d = 0; d < 64; d++) {
            float4 a = *(const float4*)&Qs[d * STR + (ty << 2)];
            ulonglong2 b = *(const ulonglong2*)&KPs[d * STR + (tx << 2)];
            unsigned long long ad;
            ad = dup2(a.x); fma2(acc[0][0], ad, b.x); fma2(acc[0][1], ad, b.y);
            ad = dup2(a.y); fma2(acc[1][0], ad, b.x); fma2(acc[1][1], ad, b.y);
            ad = dup2(a.z); fma2(acc[2][0], ad, b.x); fma2(acc[2][1], ad, b.y);
            ad = dup2(a.w); fma2(acc[3][0], ad, b.x); fma2(acc[3][1], ad, b.y);
        }

        // Register softmax over rows ty*4..ty*4+3 (16 tx lanes per row)
        float p[4][4], cf[4], mnew[4], rs[4];
#pragma unroll
        for (int i = 0; i < 4; i++) {
            float2 e0 = unpk(acc[i][0]), e1 = unpk(acc[i][1]);
            p[i][0] = e0.x; p[i][1] = e0.y; p[i][2] = e1.x; p[i][3] = e1.y;
            float m = fmaxf(fmaxf(p[i][0], p[i][1]), fmaxf(p[i][2], p[i][3]));
#pragma unroll
            for (int off = 1; off < 16; off <<= 1)
                m = fmaxf(m, __shfl_xor_sync(0xffffffffu, m, off));
            const float mold = mrow[(ty << 2) + i];
            mnew[i] = fmaxf(mold, m);
            cf[i] = __expf(mold - mnew[i]);
            float s = 0.f;
#pragma unroll
            for (int j = 0; j < 4; j++) {
                p[i][j] = __expf(p[i][j] - mnew[i]);
                s += p[i][j];
            }
#pragma unroll
            for (int off = 1; off < 16; off <<= 1)
                s += __shfl_xor_sync(0xffffffffu, s, off);
            rs[i] = s;
        }
        __syncwarp();
        if (tx == 0) {
#pragma unroll
            for (int i = 0; i < 4; i++) {
                const int r = (ty << 2) + i;
                mrow[r] = mnew[i];
                lrow[r] = lrow[r] * cf[i] + rs[i];
            }
        }

        __syncthreads();   // all QK reads of KPs done -> safe to overwrite with P^T
#pragma unroll
        for (int j = 0; j < 4; j++)
            *(float4*)&KPs[((tx << 2) + j) * STR + (ty << 2)] =
                make_float4(p[0][j], p[1][j], p[2][j], p[3][j]);
        __syncthreads();   // P^T visible

        // O = O*cf + P @ V
#pragma unroll
        for (int i = 0; i < 4; i++) {
            unsigned long long c2 = dup2(cf[i]);
            op[i][0] = mul2(op[i][0], c2);
            op[i][1] = mul2(op[i][1], c2);
        }
#pragma unroll 8
        for (int k = 0; k < 64; k++) {
            float4 pr = *(const float4*)&KPs[k * STR + (ty << 2)];   // P[r..r+3][k]
            ulonglong2 vv = *(const ulonglong2*)&Vs[k * STR + (tx << 2)];
            unsigned long long ad;
            ad = dup2(pr.x); fma2(op[0][0], ad, vv.x); fma2(op[0][1], ad, vv.y);
            ad = dup2(pr.y); fma2(op[1][0], ad, vv.x); fma2(op[1][1], ad, vv.y);
            ad = dup2(pr.z); fma2(op[2][0], ad, vv.x); fma2(op[2][1], ad, vv.y);
            ad = dup2(pr.w); fma2(op[3][0], ad, vv.x); fma2(op[3][1], ad, vv.y);
        }
    }
    __syncthreads();

    // Normalize and write out[t][h*64 + d]
#pragma unroll
    for (int i = 0; i < 4; i++) {
        const int t = q0 + (ty << 2) + i;
        const float inv = 1.f / lrow[(ty << 2) + i];
        float2 e0 = unpk(op[i][0]), e1 = unpk(op[i][1]);
        *(float4*)&out[t * HID + h * HD + (tx << 2)] =
            make_float4(e0.x * inv, e0.y * inv, e1.x * inv, e1.y * inv);
    }
}

// ---------------------------------------------------------------------------
extern "C" void kernel_launch(void* const* d_in, const int* in_sizes, int n_in,
                              void* d_out, int out_size) {
    const float* x = (const float*)d_in[0];       // [1, 4096, 1024] fp32
    const float* W = (const float*)d_in[1];       // [1024, 3072]  fp32
    float* out = (float*)d_out;                   // [1, 4096, 1024] fp32

    dim3 ggrid(3 * HID / 128, TSEQ / 128);        // (24, 32)
    qkv_gemm_kernel<<<ggrid, 256>>>(x, W);

    cudaFuncSetAttribute(flash_attn_kernel,
                         cudaFuncAttributeMaxDynamicSharedMemorySize,
                         ATTN_SMEM_BYTES);
    dim3 agrid(TSEQ / 64, NH);                    // (64, 16)
    flash_attn_kernel<<<agrid, 256, ATTN_SMEM_BYTES>>>(out);
}

// round 8
// speedup vs baseline: 1.0010x; 1.0010x over previous
#include <cuda_runtime.h>

#define TSEQ 4096
#define HID  1024
#define NH   16
#define HD   64
#define STR  68

// Scratch for Q, K, V in [head][token][dh] layout (16 MB each).
__device__ float g_q[NH * TSEQ * HD];
__device__ float g_k[NH * TSEQ * HD];
__device__ float g_v[NH * TSEQ * HD];

// ---------------------------------------------------------------------------
// Packed fp32x2 helpers (sm_10x).
// ---------------------------------------------------------------------------
__device__ __forceinline__ unsigned long long dup2(float x) {
    unsigned long long r;
    unsigned u = __float_as_uint(x);
    asm("mov.b64 %0, {%1, %1};" : "=l"(r) : "r"(u));
    return r;
}
__device__ __forceinline__ void fma2(unsigned long long& d,
                                     unsigned long long a, unsigned long long b) {
    asm("fma.rn.f32x2 %0, %1, %2, %0;" : "+l"(d) : "l"(a), "l"(b));
}
__device__ __forceinline__ unsigned long long mul2(unsigned long long a,
                                                   unsigned long long b) {
    unsigned long long r;
    asm("mul.rn.f32x2 %0, %1, %2;" : "=l"(r) : "l"(a), "l"(b));
    return r;
}
__device__ __forceinline__ float2 unpk(unsigned long long v) {
    unsigned lo, hi;
    asm("mov.b64 {%0, %1}, %2;" : "=r"(lo), "=r"(hi) : "l"(v));
    return make_float2(__uint_as_float(lo), __uint_as_float(hi));
}

// ---------------------------------------------------------------------------
// Kernel 1: QKV GEMM. 128x128 tile, BK=16, 256 threads, 8x8 frag, f32x2,
// B pairs via ulonglong2 shared loads, 2 CTAs/SM.
// ---------------------------------------------------------------------------
#define GSTR 132

__global__ __launch_bounds__(256, 2) void qkv_gemm_kernel(const float* __restrict__ x,
                                                          const float* __restrict__ W) {
    __shared__ float As[16][GSTR];   // As[k][m]
    __shared__ float Bs[16][GSTR];   // Bs[k][n]

    const int tid = threadIdx.x;
    const int tx = tid & 15, ty = tid >> 4;
    const int n0 = blockIdx.x * 128;
    const int m0 = blockIdx.y * 128;

    const int arow = tid >> 1;            // 0..127
    const int acol = (tid & 1) << 3;      // 0 or 8
    const int brow = tid >> 4;            // 0..15
    const int bcol = (tid & 15) << 3;     // 0..120

    float4 a0 = *(const float4*)&x[(m0 + arow) * HID + acol];
    float4 a1 = *(const float4*)&x[(m0 + arow) * HID + acol + 4];
    float4 b0 = *(const float4*)&W[brow * (3 * HID) + n0 + bcol];
    float4 b1 = *(const float4*)&W[brow * (3 * HID) + n0 + bcol + 4];

    unsigned long long acc[8][4] = {};

    for (int k0 = 0; k0 < HID; k0 += 16) {
        As[acol + 0][arow] = a0.x; As[acol + 1][arow] = a0.y;
        As[acol + 2][arow] = a0.z; As[acol + 3][arow] = a0.w;
        As[acol + 4][arow] = a1.x; As[acol + 5][arow] = a1.y;
        As[acol + 6][arow] = a1.z; As[acol + 7][arow] = a1.w;
        *(float4*)&Bs[brow][bcol] = b0;
        *(float4*)&Bs[brow][bcol + 4] = b1;
        __syncthreads();

        if (k0 + 16 < HID) {
            a0 = *(const float4*)&x[(m0 + arow) * HID + k0 + 16 + acol];
            a1 = *(const float4*)&x[(m0 + arow) * HID + k0 + 16 + acol + 4];
            b0 = *(const float4*)&W[(k0 + 16 + brow) * (3 * HID) + n0 + bcol];
            b1 = *(const float4*)&W[(k0 + 16 + brow) * (3 * HID) + n0 + bcol + 4];
        }

#pragma unroll
        for (int kk = 0; kk < 16; kk++) {
            float4 aA = *(float4*)&As[kk][ty << 3];
            float4 aB = *(float4*)&As[kk][(ty << 3) + 4];
            ulonglong2 bA = *(ulonglong2*)&Bs[kk][tx << 3];
            ulonglong2 bB = *(ulonglong2*)&Bs[kk][(tx << 3) + 4];
            unsigned long long bp[4] = {bA.x, bA.y, bB.x, bB.y};
            float av[8] = {aA.x, aA.y, aA.z, aA.w, aB.x, aB.y, aB.z, aB.w};
#pragma unroll
            for (int i = 0; i < 8; i++) {
                unsigned long long ad = dup2(av[i]);
#pragma unroll
                for (int jp = 0; jp < 4; jp++) fma2(acc[i][jp], ad, bp[jp]);
            }
        }
        __syncthreads();
    }

    const int s = n0 / HID;
    float* dst = (s == 0) ? g_q : (s == 1) ? g_k : g_v;
    const int col = (n0 % HID) + (tx << 3);
    const int hh = col / HD;
    const int dd = col % HD;

#pragma unroll
    for (int i = 0; i < 8; i++) {
        const int t = m0 + (ty << 3) + i;
        float2 e0 = unpk(acc[i][0]), e1 = unpk(acc[i][1]);
        float2 e2 = unpk(acc[i][2]), e3 = unpk(acc[i][3]);
        float* p = &dst[(hh * TSEQ + t) * HD + dd];
        *(float4*)p       = make_float4(e0.x, e0.y, e1.x, e1.y);
        *(float4*)(p + 4) = make_float4(e2.x, e2.y, e3.x, e3.y);
    }
}

// ---------------------------------------------------------------------------
// Kernel 2: flash attention, 64q x 64k tile, 256 threads, 3 CTAs/SM.
// Register softmax; P^T overwrites the K buffer (dead after QK).
// Thread grid 16(tx: cols/dims) x 16(ty: row groups), 4x4 fragments,
// accumulator pairs along tx via f32x2.
// ---------------------------------------------------------------------------
#define ATTN_SMEM_FLOATS (3 * 64 * STR + 128)
#define ATTN_SMEM_BYTES  (ATTN_SMEM_FLOATS * 4)

__global__ __launch_bounds__(256, 3) void flash_attn_kernel(float* __restrict__ out) {
    extern __shared__ float smf[];
    float* Qs   = smf;                 // [d][r]  64 x STR (Q^T, pre-scaled)
    float* KPs  = Qs + 64 * STR;       // [d][c] K^T, then [c][r] P^T
    float* Vs   = KPs + 64 * STR;      // [k][d]
    float* mrow = Vs + 64 * STR;       // [64]
    float* lrow = mrow + 64;           // [64]

    const int tid = threadIdx.x;
    const int tx = tid & 15, ty = tid >> 4;
    const int h  = blockIdx.y;
    const int q0 = blockIdx.x * 64;

    const float* Qg = g_q + h * TSEQ * HD;
    const float* Kg = g_k + h * TSEQ * HD;
    const float* Vg = g_v + h * TSEQ * HD;

    const int lr = tid >> 2;           // 0..63 load row
    const int ds = (tid & 3) << 4;     // 0,16,32,48

    // Q^T, scaled by 1/sqrt(64)
#pragma unroll
    for (int c = 0; c < 4; c++) {
        const int d = ds + c * 4;
        float4 v = *(const float4*)&Qg[(q0 + lr) * HD + d];
        Qs[(d + 0) * STR + lr] = v.x * 0.125f;
        Qs[(d + 1) * STR + lr] = v.y * 0.125f;
        Qs[(d + 2) * STR + lr] = v.z * 0.125f;
        Qs[(d + 3) * STR + lr] = v.w * 0.125f;
    }
    if (tid < 64) { mrow[tid] = -1e30f; lrow[tid] = 0.f; }

    unsigned long long op[4][2] = {};   // O: rows ty*4+i, dim pairs tx*4+2jp

    for (int kb = 0; kb < TSEQ / 64; kb++) {
        const int c0 = kb * 64;
        __syncthreads();   // prev PV done reading KPs/Vs (and Q/stats on iter 0)

        // Stage K^T into KPs, V into Vs
#pragma unroll
        for (int c = 0; c < 4; c++) {
            const int d = ds + c * 4;
            float4 kv = *(const float4*)&Kg[(c0 + lr) * HD + d];
            KPs[(d + 0) * STR + lr] = kv.x;
            KPs[(d + 1) * STR + lr] = kv.y;
            KPs[(d + 2) * STR + lr] = kv.z;
            KPs[(d + 3) * STR + lr] = kv.w;
            *(float4*)&Vs[lr * STR + d] = *(const float4*)&Vg[(c0 + lr) * HD + d];
        }
        __syncthreads();

        // S = Q @ K^T : acc[i][jp] = S[ty*4+i][tx*4+2jp .. +1]
        unsigned long long acc[4][2] = {};
#pragma unroll 8
        for (int d = 0; d < 64; d++) {
            float4 a = *(const float4*)&Qs[d * STR + (ty << 2)];
            ulonglong2 b = *(const ulonglong2*)&KPs[d * STR + (tx << 2)];
            unsigned long long ad;
            ad = dup2(a.x); fma2(acc[0][0], ad, b.x); fma2(acc[0][1], ad, b.y);
            ad = dup2(a.y); fma2(acc[1][0], ad, b.x); fma2(acc[1][1], ad, b.y);
            ad = dup2(a.z); fma2(acc[2][0], ad, b.x); fma2(acc[2][1], ad, b.y);
            ad = dup2(a.w); fma2(acc[3][0], ad, b.x); fma2(acc[3][1], ad, b.y);
        }

        // Register softmax over rows ty*4..ty*4+3 (16 tx lanes per row)
        float p[4][4], cf[4], mnew[4], rs[4];
#pragma unroll
        for (int i = 0; i < 4; i++) {
            float2 e0 = unpk(acc[i][0]), e1 = unpk(acc[i][1]);
            p[i][0] = e0.x; p[i][1] = e0.y; p[i][2] = e1.x; p[i][3] = e1.y;
            float m = fmaxf(fmaxf(p[i][0], p[i][1]), fmaxf(p[i][2], p[i][3]));
#pragma unroll
            for (int off = 1; off < 16; off <<= 1)
                m = fmaxf(m, __shfl_xor_sync(0xffffffffu, m, off));
            const float mold = mrow[(ty << 2) + i];
            mnew[i] = fmaxf(mold, m);
            cf[i] = __expf(mold - mnew[i]);
            float s = 0.f;
#pragma unroll
            for (int j = 0; j < 4; j++) {
                p[i][j] = __expf(p[i][j] - mnew[i]);
                s += p[i][j];
            }
#pragma unroll
            for (int off = 1; off < 16; off <<= 1)
                s += __shfl_xor_sync(0xffffffffu, s, off);
            rs[i] = s;
        }
        __syncwarp();
        if (tx == 0) {
#pragma unroll
            for (int i = 0; i < 4; i++) {
                const int r = (ty << 2) + i;
                mrow[r] = mnew[i];
                lrow[r] = lrow[r] * cf[i] + rs[i];
            }
        }

        __syncthreads();   // all QK reads of KPs done -> safe to overwrite with P^T
#pragma unroll
        for (int j = 0; j < 4; j++)
            *(float4*)&KPs[((tx << 2) + j) * STR + (ty << 2)] =
                make_float4(p[0][j], p[1][j], p[2][j], p[3][j]);
        __syncthreads();   // P^T visible

        // O = O*cf + P @ V
#pragma unroll
        for (int i = 0; i < 4; i++) {
            unsigned long long c2 = dup2(cf[i]);
            op[i][0] = mul2(op[i][0], c2);
            op[i][1] = mul2(op[i][1], c2);
        }
#pragma unroll 8
        for (int k = 0; k < 64; k++) {
            float4 pr = *(const float4*)&KPs[k * STR + (ty << 2)];   // P[r..r+3][k]
            ulonglong2 vv = *(const ulonglong2*)&Vs[k * STR + (tx << 2)];
            unsigned long long ad;
            ad = dup2(pr.x); fma2(op[0][0], ad, vv.x); fma2(op[0][1], ad, vv.y);
            ad = dup2(pr.y); fma2(op[1][0], ad, vv.x); fma2(op[1][1], ad, vv.y);
            ad = dup2(pr.z); fma2(op[2][0], ad, vv.x); fma2(op[2][1], ad, vv.y);
            ad = dup2(pr.w); fma2(op[3][0], ad, vv.x); fma2(op[3][1], ad, vv.y);
        }
    }
    __syncthreads();

    // Normalize and write out[t][h*64 + d]
#pragma unroll
    for (int i = 0; i < 4; i++) {
        const int t = q0 + (ty << 2) + i;
        const float inv = 1.f / lrow[(ty << 2) + i];
        float2 e0 = unpk(op[i][0]), e1 = unpk(op[i][1]);
        *(float4*)&out[t * HID + h * HD + (tx << 2)] =
            make_float4(e0.x * inv, e0.y * inv, e1.x * inv, e1.y * inv);
    }
}

// ---------------------------------------------------------------------------
extern "C" void kernel_launch(void* const* d_in, const int* in_sizes, int n_in,
                              void* d_out, int out_size) {
    const float* x = (const float*)d_in[0];       // [1, 4096, 1024] fp32
    const float* W = (const float*)d_in[1];       // [1024, 3072]  fp32
    float* out = (float*)d_out;                   // [1, 4096, 1024] fp32

    dim3 ggrid(3 * HID / 128, TSEQ / 128);        // (24, 32)
    qkv_gemm_kernel<<<ggrid, 256>>>(x, W);

    cudaFuncSetAttribute(flash_attn_kernel,
                         cudaFuncAttributeMaxDynamicSharedMemorySize,
                         ATTN_SMEM_BYTES);
    dim3 agrid(TSEQ / 64, NH);                    // (64, 16)
    flash_attn_kernel<<<agrid, 256, ATTN_SMEM_BYTES>>>(out);
}

// round 9
// speedup vs baseline: 1.0019x; 1.0009x over previous
#include <cuda_runtime.h>

#define TSEQ 4096
#define HID  1024
#define NH   16
#define HD   64
#define STR  68

// Scratch for Q, K, V in [head][token][dh] layout (16 MB each).
__device__ float g_q[NH * TSEQ * HD];
__device__ float g_k[NH * TSEQ * HD];
__device__ float g_v[NH * TSEQ * HD];

// ---------------------------------------------------------------------------
// Packed fp32x2 helpers (sm_10x).
// ---------------------------------------------------------------------------
__device__ __forceinline__ unsigned long long dup2(float x) {
    unsigned long long r;
    unsigned u = __float_as_uint(x);
    asm("mov.b64 %0, {%1, %1};" : "=l"(r) : "r"(u));
    return r;
}
__device__ __forceinline__ void fma2(unsigned long long& d,
                                     unsigned long long a, unsigned long long b) {
    asm("fma.rn.f32x2 %0, %1, %2, %0;" : "+l"(d) : "l"(a), "l"(b));
}
__device__ __forceinline__ unsigned long long mul2(unsigned long long a,
                                                   unsigned long long b) {
    unsigned long long r;
    asm("mul.rn.f32x2 %0, %1, %2;" : "=l"(r) : "l"(a), "l"(b));
    return r;
}
__device__ __forceinline__ float2 unpk(unsigned long long v) {
    unsigned lo, hi;
    asm("mov.b64 {%0, %1}, %2;" : "=r"(lo), "=r"(hi) : "l"(v));
    return make_float2(__uint_as_float(lo), __uint_as_float(hi));
}

// ---------------------------------------------------------------------------
// Kernel 1: QKV GEMM. 128x128 tile, BK=16, 256 threads, 8x8 frag, f32x2,
// B pairs via ulonglong2 shared loads, 2 CTAs/SM.
// ---------------------------------------------------------------------------
#define GSTR 132

__global__ __launch_bounds__(256, 2) void qkv_gemm_kernel(const float* __restrict__ x,
                                                          const float* __restrict__ W) {
    __shared__ float As[16][GSTR];   // As[k][m]
    __shared__ float Bs[16][GSTR];   // Bs[k][n]

    const int tid = threadIdx.x;
    const int tx = tid & 15, ty = tid >> 4;
    const int n0 = blockIdx.x * 128;
    const int m0 = blockIdx.y * 128;

    const int arow = tid >> 1;            // 0..127
    const int acol = (tid & 1) << 3;      // 0 or 8
    const int brow = tid >> 4;            // 0..15
    const int bcol = (tid & 15) << 3;     // 0..120

    float4 a0 = *(const float4*)&x[(m0 + arow) * HID + acol];
    float4 a1 = *(const float4*)&x[(m0 + arow) * HID + acol + 4];
    float4 b0 = *(const float4*)&W[brow * (3 * HID) + n0 + bcol];
    float4 b1 = *(const float4*)&W[brow * (3 * HID) + n0 + bcol + 4];

    unsigned long long acc[8][4] = {};

    for (int k0 = 0; k0 < HID; k0 += 16) {
        As[acol + 0][arow] = a0.x; As[acol + 1][arow] = a0.y;
        As[acol + 2][arow] = a0.z; As[acol + 3][arow] = a0.w;
        As[acol + 4][arow] = a1.x; As[acol + 5][arow] = a1.y;
        As[acol + 6][arow] = a1.z; As[acol + 7][arow] = a1.w;
        *(float4*)&Bs[brow][bcol] = b0;
        *(float4*)&Bs[brow][bcol + 4] = b1;
        __syncthreads();

        if (k0 + 16 < HID) {
            a0 = *(const float4*)&x[(m0 + arow) * HID + k0 + 16 + acol];
            a1 = *(const float4*)&x[(m0 + arow) * HID + k0 + 16 + acol + 4];
            b0 = *(const float4*)&W[(k0 + 16 + brow) * (3 * HID) + n0 + bcol];
            b1 = *(const float4*)&W[(k0 + 16 + brow) * (3 * HID) + n0 + bcol + 4];
        }

#pragma unroll
        for (int kk = 0; kk < 16; kk++) {
            float4 aA = *(float4*)&As[kk][ty << 3];
            float4 aB = *(float4*)&As[kk][(ty << 3) + 4];
            ulonglong2 bA = *(ulonglong2*)&Bs[kk][tx << 3];
            ulonglong2 bB = *(ulonglong2*)&Bs[kk][(tx << 3) + 4];
            unsigned long long bp[4] = {bA.x, bA.y, bB.x, bB.y};
            float av[8] = {aA.x, aA.y, aA.z, aA.w, aB.x, aB.y, aB.z, aB.w};
#pragma unroll
            for (int i = 0; i < 8; i++) {
                unsigned long long ad = dup2(av[i]);
#pragma unroll
                for (int jp = 0; jp < 4; jp++) fma2(acc[i][jp], ad, bp[jp]);
            }
        }
        __syncthreads();
    }

    const int s = n0 / HID;
    float* dst = (s == 0) ? g_q : (s == 1) ? g_k : g_v;
    const int col = (n0 % HID) + (tx << 3);
    const int hh = col / HD;
    const int dd = col % HD;

#pragma unroll
    for (int i = 0; i < 8; i++) {
        const int t = m0 + (ty << 3) + i;
        float2 e0 = unpk(acc[i][0]), e1 = unpk(acc[i][1]);
        float2 e2 = unpk(acc[i][2]), e3 = unpk(acc[i][3]);
        float* p = &dst[(hh * TSEQ + t) * HD + dd];
        *(float4*)p       = make_float4(e0.x, e0.y, e1.x, e1.y);
        *(float4*)(p + 4) = make_float4(e2.x, e2.y, e3.x, e3.y);
    }
}

// ---------------------------------------------------------------------------
// Kernel 2: flash attention, 64q x 64k tile, 256 threads, 3 CTAs/SM.
// Register softmax; P^T overwrites the K buffer (dead after QK).
// Thread grid 16(tx: cols/dims) x 16(ty: row groups), 4x4 fragments,
// accumulator pairs along tx via f32x2.
// ---------------------------------------------------------------------------
#define ATTN_SMEM_FLOATS (3 * 64 * STR + 128)
#define ATTN_SMEM_BYTES  (ATTN_SMEM_FLOATS * 4)

__global__ __launch_bounds__(256, 3) void flash_attn_kernel(float* __restrict__ out) {
    extern __shared__ float smf[];
    float* Qs   = smf;                 // [d][r]  64 x STR (Q^T, pre-scaled)
    float* KPs  = Qs + 64 * STR;       // [d][c] K^T, then [c][r] P^T
    float* Vs   = KPs + 64 * STR;      // [k][d]
    float* mrow = Vs + 64 * STR;       // [64]
    float* lrow = mrow + 64;           // [64]

    const int tid = threadIdx.x;
    const int tx = tid & 15, ty = tid >> 4;
    const int h  = blockIdx.y;
    const int q0 = blockIdx.x * 64;

    const float* Qg = g_q + h * TSEQ * HD;
    const float* Kg = g_k + h * TSEQ * HD;
    const float* Vg = g_v + h * TSEQ * HD;

    const int lr = tid >> 2;           // 0..63 load row
    const int ds = (tid & 3) << 4;     // 0,16,32,48

    // Q^T, scaled by 1/sqrt(64)
#pragma unroll
    for (int c = 0; c < 4; c++) {
        const int d = ds + c * 4;
        float4 v = *(const float4*)&Qg[(q0 + lr) * HD + d];
        Qs[(d + 0) * STR + lr] = v.x * 0.125f;
        Qs[(d + 1) * STR + lr] = v.y * 0.125f;
        Qs[(d + 2) * STR + lr] = v.z * 0.125f;
        Qs[(d + 3) * STR + lr] = v.w * 0.125f;
    }
    if (tid < 64) { mrow[tid] = -1e30f; lrow[tid] = 0.f; }

    unsigned long long op[4][2] = {};   // O: rows ty*4+i, dim pairs tx*4+2jp

    for (int kb = 0; kb < TSEQ / 64; kb++) {
        const int c0 = kb * 64;
        __syncthreads();   // prev PV done reading KPs/Vs (and Q/stats on iter 0)

        // Stage K^T into KPs, V into Vs
#pragma unroll
        for (int c = 0; c < 4; c++) {
            const int d = ds + c * 4;
            float4 kv = *(const float4*)&Kg[(c0 + lr) * HD + d];
            KPs[(d + 0) * STR + lr] = kv.x;
            KPs[(d + 1) * STR + lr] = kv.y;
            KPs[(d + 2) * STR + lr] = kv.z;
            KPs[(d + 3) * STR + lr] = kv.w;
            *(float4*)&Vs[lr * STR + d] = *(const float4*)&Vg[(c0 + lr) * HD + d];
        }
        __syncthreads();

        // S = Q @ K^T : acc[i][jp] = S[ty*4+i][tx*4+2jp .. +1]
        unsigned long long acc[4][2] = {};
#pragma unroll 8
        for (int d = 0; d < 64; d++) {
            float4 a = *(const float4*)&Qs[d * STR + (ty << 2)];
            ulonglong2 b = *(const ulonglong2*)&KPs[d * STR + (tx << 2)];
            unsigned long long ad;
            ad = dup2(a.x); fma2(acc[0][0], ad, b.x); fma2(acc[0][1], ad, b.y);
            ad = dup2(a.y); fma2(acc[1][0], ad, b.x); fma2(acc[1][1], ad, b.y);
            ad = dup2(a.z); fma2(acc[2][0], ad, b.x); fma2(acc[2][1], ad, b.y);
            ad = dup2(a.w); fma2(acc[3][0], ad, b.x); fma2(acc[3][1], ad, b.y);
        }

        // Register softmax over rows ty*4..ty*4+3 (16 tx lanes per row)
        float p[4][4], cf[4], mnew[4], rs[4];
#pragma unroll
        for (int i = 0; i < 4; i++) {
            float2 e0 = unpk(acc[i][0]), e1 = unpk(acc[i][1]);
            p[i][0] = e0.x; p[i][1] = e0.y; p[i][2] = e1.x; p[i][3] = e1.y;
            float m = fmaxf(fmaxf(p[i][0], p[i][1]), fmaxf(p[i][2], p[i][3]));
#pragma unroll
            for (int off = 1; off < 16; off <<= 1)
                m = fmaxf(m, __shfl_xor_sync(0xffffffffu, m, off));
            const float mold = mrow[(ty << 2) + i];
            mnew[i] = fmaxf(mold, m);
            cf[i] = __expf(mold - mnew[i]);
            float s = 0.f;
#pragma unroll
            for (int j = 0; j < 4; j++) {
                p[i][j] = __expf(p[i][j] - mnew[i]);
                s += p[i][j];
            }
#pragma unroll
            for (int off = 1; off < 16; off <<= 1)
                s += __shfl_xor_sync(0xffffffffu, s, off);
            rs[i] = s;
        }
        __syncwarp();
        if (tx == 0) {
#pragma unroll
            for (int i = 0; i < 4; i++) {
                const int r = (ty << 2) + i;
                mrow[r] = mnew[i];
                lrow[r] = lrow[r] * cf[i] + rs[i];
            }
        }

        __syncthreads();   // all QK reads of KPs done -> safe to overwrite with P^T
#pragma unroll
        for (int j = 0; j < 4; j++)
            *(float4*)&KPs[((tx << 2) + j) * STR + (ty << 2)] =
                make_float4(p[0][j], p[1][j], p[2][j], p[3][j]);
        __syncthreads();   // P^T visible

        // O = O*cf + P @ V
#pragma unroll
        for (int i = 0; i < 4; i++) {
            unsigned long long c2 = dup2(cf[i]);
            op[i][0] = mul2(op[i][0], c2);
            op[i][1] = mul2(op[i][1], c2);
        }
#pragma unroll 8
        for (int k = 0; k < 64; k++) {
            float4 pr = *(const float4*)&KPs[k * STR + (ty << 2)];   // P[r..r+3][k]
            ulonglong2 vv = *(const ulonglong2*)&Vs[k * STR + (tx << 2)];
            unsigned long long ad;
            ad = dup2(pr.x); fma2(op[0][0], ad, vv.x); fma2(op[0][1], ad, vv.y);
            ad = dup2(pr.y); fma2(op[1][0], ad, vv.x); fma2(op[1][1], ad, vv.y);
            ad = dup2(pr.z); fma2(op[2][0], ad, vv.x); fma2(op[2][1], ad, vv.y);
            ad = dup2(pr.w); fma2(op[3][0], ad, vv.x); fma2(op[3][1], ad, vv.y);
        }
    }
    __syncthreads();

    // Normalize and write out[t][h*64 + d]
#pragma unroll
    for (int i = 0; i < 4; i++) {
        const int t = q0 + (ty << 2) + i;
        const float inv = 1.f / lrow[(ty << 2) + i];
        float2 e0 = unpk(op[i][0]), e1 = unpk(op[i][1]);
        *(float4*)&out[t * HID + h * HD + (tx << 2)] =
            make_float4(e0.x * inv, e0.y * inv, e1.x * inv, e1.y * inv);
    }
}

// ---------------------------------------------------------------------------
extern "C" void kernel_launch(void* const* d_in, const int* in_sizes, int n_in,
                              void* d_out, int out_size) {
    const float* x = (const float*)d_in[0];       // [1, 4096, 1024] fp32
    const float* W = (const float*)d_in[1];       // [1024, 3072]  fp32
    float* out = (float*)d_out;                   // [1, 4096, 1024] fp32

    dim3 ggrid(3 * HID / 128, TSEQ / 128);        // (24, 32)
    qkv_gemm_kernel<<<ggrid, 256>>>(x, W);

    cudaFuncSetAttribute(flash_attn_kernel,
                         cudaFuncAttributeMaxDynamicSharedMemorySize,
                         ATTN_SMEM_BYTES);
    dim3 agrid(TSEQ / 64, NH);                    // (64, 16)
    flash_attn_kernel<<<agrid, 256, ATTN_SMEM_BYTES>>>(out);
}